// round 4
// baseline (speedup 1.0000x reference)
#include <cuda_runtime.h>
#include <cstdint>

// Problem constants (fixed shapes from reference)
#define BB 8
#define NVV 8192
#define EE 32768

// Scratch (no cudaMalloc allowed): M in (e, bc) layout + L_vert accumulator
__device__ float g_M[EE * 24];       // 3 MB:  M[e][b*3+c]
__device__ float g_Lv[24 * NVV];     // 768 KB: Lv[bc][n]

// ---------------------------------------------------------------------------
// Kernel 0: zero the L_vert accumulator (graph replays re-run this each launch)
// ---------------------------------------------------------------------------
__global__ void k_zero() {
    int t = blockIdx.x * blockDim.x + threadIdx.x;
    if (t < 24 * NVV) g_Lv[t] = 0.0f;
}

// ---------------------------------------------------------------------------
// Kernel 1: per-(b,e) constraint solve -> L_new (into d_out tail) + M scratch
// ---------------------------------------------------------------------------
__global__ void k_edge(const float* __restrict__ Vp,     // (B,NV,3)
                       const float* __restrict__ L,      // (B,E,1)
                       const float* __restrict__ Vw,     // (B,NV,1)
                       const float* __restrict__ Vc,     // (B,1,1)
                       const int*   __restrict__ Cd,     // (E,2)
                       const float* __restrict__ Cid,    // (E,1)
                       float*       __restrict__ Lnew)   // (B,E) at d_out + B*NV*3
{
    int tid = blockIdx.x * blockDim.x + threadIdx.x;
    if (tid >= BB * EE) return;
    int b = tid / EE;
    int e = tid - b * EE;

    int i = Cd[2 * e];
    int j = Cd[2 * e + 1];

    const float* pi = Vp + ((size_t)b * NVV + i) * 3;
    const float* pj = Vp + ((size_t)b * NVV + j) * 3;
    float nx = pi[0] - pj[0];
    float ny = pi[1] - pj[1];
    float nz = pi[2] - pj[2];
    float D = sqrtf(nx * nx + ny * ny + nz * nz);
    float C = D - Cid[e];

    float A = Vc[b];
    float S = Vw[b * NVV + i] + Vw[b * NVV + j];
    float Seff = (S == 0.0f) ? __int_as_float(0x7f800000) : S;   // inf where S==0
    float denom = Seff + A;

    float l  = L[tid];                  // L is (B,E) contiguous, tid = b*E+e
    float ld = (-C - A * l) / denom;    // -> 0 when denom == inf
    Lnew[tid] = l + ld;

    float inv = ld / (D + 1e-8f);       // L_delta * N_norm
    int mb = e * 24 + b * 3;
    g_M[mb + 0] = inv * nx;
    g_M[mb + 1] = inv * ny;
    g_M[mb + 2] = inv * nz;
}

// ---------------------------------------------------------------------------
// Kernel 2: Lv[bc][n] = sum_e M[e][bc] * C_mtx[e][n]
// Tall-skinny GEMM (24 x E) * (E x NV) using packed fp32x2 FMA (FFMA2).
// 128 threads/block, 4 columns/thread, M chunk staged in SMEM as (m,m) pairs.
// Grid: (NV/512 = 16 column blocks, 32 E-chunks of 1024). Partial sums via
// float atomicAdd into g_Lv.
// ---------------------------------------------------------------------------
#define GEMM_THREADS 128
#define E_CHUNK 1024
#define E_TILE 32

__global__ void __launch_bounds__(GEMM_THREADS)
k_gemm(const float* __restrict__ Cm)   // C_mtx (E, NV) row-major
{
    __shared__ unsigned long long Ms[E_TILE][24];   // (m,m) duplicated pairs

    const int t  = threadIdx.x;
    const int n0 = blockIdx.x * (GEMM_THREADS * 4) + t * 4;  // 4 cols per thread
    const int e0 = blockIdx.y * E_CHUNK;

    unsigned long long acc0[24];   // cols n0, n0+1
    unsigned long long acc1[24];   // cols n0+2, n0+3
#pragma unroll
    for (int bc = 0; bc < 24; bc++) { acc0[bc] = 0ull; acc1[bc] = 0ull; }

    for (int et = 0; et < E_CHUNK; et += E_TILE) {
        // Stage E_TILE*24 = 768 M values as duplicated f32x2 pairs (coalesced read)
        const float* msrc = g_M + (size_t)(e0 + et) * 24;
#pragma unroll
        for (int k = t; k < E_TILE * 24; k += GEMM_THREADS) {
            unsigned long long d = (unsigned long long)__float_as_uint(msrc[k]);
            d |= d << 32;
            ((unsigned long long*)Ms)[k] = d;
        }
        __syncthreads();

        const float* p = Cm + (size_t)(e0 + et) * NVV + n0;
#pragma unroll 4
        for (int ee = 0; ee < E_TILE; ee++) {
            // 16B coalesced load: 4 consecutive columns of row e
            ulonglong2 cv = *reinterpret_cast<const ulonglong2*>(p);
            p += NVV;
#pragma unroll
            for (int bc = 0; bc < 24; bc++) {
                unsigned long long m = Ms[ee][bc];
                asm("fma.rn.f32x2 %0, %1, %2, %0;"
                    : "+l"(acc0[bc]) : "l"(m), "l"(cv.x));
                asm("fma.rn.f32x2 %0, %1, %2, %0;"
                    : "+l"(acc1[bc]) : "l"(m), "l"(cv.y));
            }
        }
        __syncthreads();
    }

    // Combine partials across E-chunks
#pragma unroll
    for (int bc = 0; bc < 24; bc++) {
        float* dst = g_Lv + (size_t)bc * NVV + n0;
        atomicAdd(dst + 0, __uint_as_float((unsigned)(acc0[bc] & 0xffffffffu)));
        atomicAdd(dst + 1, __uint_as_float((unsigned)(acc0[bc] >> 32)));
        atomicAdd(dst + 2, __uint_as_float((unsigned)(acc1[bc] & 0xffffffffu)));
        atomicAdd(dst + 3, __uint_as_float((unsigned)(acc1[bc] >> 32)));
    }
}

// ---------------------------------------------------------------------------
// Kernel 3: V_predict_new = V_predict + V_w * L_vert
// ---------------------------------------------------------------------------
__global__ void k_epi(const float* __restrict__ Vp,
                      const float* __restrict__ Vw,
                      float*       __restrict__ out)     // (B,NV,3) at d_out
{
    int tid = blockIdx.x * blockDim.x + threadIdx.x;
    if (tid >= BB * NVV) return;
    int b = tid / NVV;
    int n = tid - b * NVV;
    float w = Vw[tid];
    size_t o = (size_t)tid * 3;
    out[o + 0] = Vp[o + 0] + w * g_Lv[(size_t)(b * 3 + 0) * NVV + n];
    out[o + 1] = Vp[o + 1] + w * g_Lv[(size_t)(b * 3 + 1) * NVV + n];
    out[o + 2] = Vp[o + 2] + w * g_Lv[(size_t)(b * 3 + 2) * NVV + n];
}

// ---------------------------------------------------------------------------
extern "C" void kernel_launch(void* const* d_in, const int* in_sizes, int n_in,
                              void* d_out, int out_size)
{
    const float* Vp  = (const float*)d_in[0];   // V_predict    (B,NV,3)
    const float* L   = (const float*)d_in[1];   // L            (B,E,1)
    const float* Vw  = (const float*)d_in[2];   // V_w          (B,NV,1)
    const float* Vc  = (const float*)d_in[3];   // V_compliance (B,1,1)
    const int*   Cd  = (const int*)  d_in[4];   // C_dist       (E,2)
    const float* Cid = (const float*)d_in[5];   // C_init_d     (E,1)
    const float* Cm  = (const float*)d_in[6];   // C_mtx        (E,NV)

    float* out_vp = (float*)d_out;                         // V_predict_new
    float* out_L  = (float*)d_out + (size_t)BB * NVV * 3;  // L_new

    // 0) zero accumulator
    k_zero<<<(24 * NVV + 255) / 256, 256>>>();

    // 1) edge solve -> M, L_new
    k_edge<<<(BB * EE + 255) / 256, 256>>>(Vp, L, Vw, Vc, Cd, Cid, out_L);

    // 2) tall-skinny GEMM: Lv = M^T @ C_mtx
    dim3 g(NVV / (GEMM_THREADS * 4), EE / E_CHUNK);  // (16, 32)
    k_gemm<<<g, GEMM_THREADS>>>(Cm);

    // 3) vertex update
    k_epi<<<(BB * NVV + 255) / 256, 256>>>(Vp, Vw, out_vp);
}

// round 5
// speedup vs baseline: 1.0174x; 1.0174x over previous
#include <cuda_runtime.h>
#include <cstdint>

// Problem constants (fixed shapes from reference)
#define BB 8
#define NVV 8192
#define EE 32768

// Scratch (no cudaMalloc allowed): M in (e, bc) layout + L_vert accumulator
__device__ float g_M[EE * 24];       // 3 MB:  M[e][b*3+c]
__device__ float g_Lv[24 * NVV];     // 768 KB: Lv[bc][n]

// ---------------------------------------------------------------------------
// Kernel 0: zero the L_vert accumulator (graph replays re-run this each launch)
// ---------------------------------------------------------------------------
__global__ void k_zero() {
    int t = blockIdx.x * blockDim.x + threadIdx.x;
    if (t < 24 * NVV) g_Lv[t] = 0.0f;
}

// ---------------------------------------------------------------------------
// Kernel 1: per-(b,e) constraint solve -> L_new (into d_out tail) + M scratch
// ---------------------------------------------------------------------------
__global__ void k_edge(const float* __restrict__ Vp,     // (B,NV,3)
                       const float* __restrict__ L,      // (B,E,1)
                       const float* __restrict__ Vw,     // (B,NV,1)
                       const float* __restrict__ Vc,     // (B,1,1)
                       const int*   __restrict__ Cd,     // (E,2)
                       const float* __restrict__ Cid,    // (E,1)
                       float*       __restrict__ Lnew)   // (B,E) at d_out + B*NV*3
{
    int tid = blockIdx.x * blockDim.x + threadIdx.x;
    if (tid >= BB * EE) return;
    int b = tid / EE;
    int e = tid - b * EE;

    int i = Cd[2 * e];
    int j = Cd[2 * e + 1];

    const float* pi = Vp + ((size_t)b * NVV + i) * 3;
    const float* pj = Vp + ((size_t)b * NVV + j) * 3;
    float nx = pi[0] - pj[0];
    float ny = pi[1] - pj[1];
    float nz = pi[2] - pj[2];
    float D = sqrtf(nx * nx + ny * ny + nz * nz);
    float C = D - Cid[e];

    float A = Vc[b];
    float S = Vw[b * NVV + i] + Vw[b * NVV + j];
    float Seff = (S == 0.0f) ? __int_as_float(0x7f800000) : S;   // inf where S==0
    float denom = Seff + A;

    float l  = L[tid];                  // L is (B,E) contiguous, tid = b*E+e
    float ld = (-C - A * l) / denom;    // -> 0 when denom == inf
    Lnew[tid] = l + ld;

    float inv = ld / (D + 1e-8f);       // L_delta * N_norm
    int mb = e * 24 + b * 3;
    g_M[mb + 0] = inv * nx;
    g_M[mb + 1] = inv * ny;
    g_M[mb + 2] = inv * nz;
}

// ---------------------------------------------------------------------------
// Kernel 2: Lv[bc][n] = sum_e M[e][bc] * C_mtx[e][n]
// Tall-skinny GEMM (24 x E) * (E x NV) using packed fp32x2 FMA (FFMA2).
// 128 threads/block, 4 columns/thread, M chunk staged in SMEM as (m,m) pairs.
// Grid: (NV/512 = 16 column blocks, 32 E-chunks of 1024). Partial sums via
// float atomicAdd into g_Lv.
// ---------------------------------------------------------------------------
#define GEMM_THREADS 128
#define E_CHUNK 1024
#define E_TILE 32

__global__ void __launch_bounds__(GEMM_THREADS)
k_gemm(const float* __restrict__ Cm)   // C_mtx (E, NV) row-major
{
    __shared__ unsigned long long Ms[E_TILE][24];   // (m,m) duplicated pairs

    const int t  = threadIdx.x;
    const int n0 = blockIdx.x * (GEMM_THREADS * 4) + t * 4;  // 4 cols per thread
    const int e0 = blockIdx.y * E_CHUNK;

    unsigned long long acc0[24];   // cols n0, n0+1
    unsigned long long acc1[24];   // cols n0+2, n0+3
#pragma unroll
    for (int bc = 0; bc < 24; bc++) { acc0[bc] = 0ull; acc1[bc] = 0ull; }

    for (int et = 0; et < E_CHUNK; et += E_TILE) {
        // Stage E_TILE*24 = 768 M values as duplicated f32x2 pairs (coalesced read)
        const float* msrc = g_M + (size_t)(e0 + et) * 24;
#pragma unroll
        for (int k = t; k < E_TILE * 24; k += GEMM_THREADS) {
            unsigned long long d = (unsigned long long)__float_as_uint(msrc[k]);
            d |= d << 32;
            ((unsigned long long*)Ms)[k] = d;
        }
        __syncthreads();

        const float* p = Cm + (size_t)(e0 + et) * NVV + n0;
#pragma unroll 4
        for (int ee = 0; ee < E_TILE; ee++) {
            // 16B coalesced load: 4 consecutive columns of row e
            ulonglong2 cv = *reinterpret_cast<const ulonglong2*>(p);
            p += NVV;
#pragma unroll
            for (int bc = 0; bc < 24; bc++) {
                unsigned long long m = Ms[ee][bc];
                asm("fma.rn.f32x2 %0, %1, %2, %0;"
                    : "+l"(acc0[bc]) : "l"(m), "l"(cv.x));
                asm("fma.rn.f32x2 %0, %1, %2, %0;"
                    : "+l"(acc1[bc]) : "l"(m), "l"(cv.y));
            }
        }
        __syncthreads();
    }

    // Combine partials across E-chunks
#pragma unroll
    for (int bc = 0; bc < 24; bc++) {
        float* dst = g_Lv + (size_t)bc * NVV + n0;
        atomicAdd(dst + 0, __uint_as_float((unsigned)(acc0[bc] & 0xffffffffu)));
        atomicAdd(dst + 1, __uint_as_float((unsigned)(acc0[bc] >> 32)));
        atomicAdd(dst + 2, __uint_as_float((unsigned)(acc1[bc] & 0xffffffffu)));
        atomicAdd(dst + 3, __uint_as_float((unsigned)(acc1[bc] >> 32)));
    }
}

// ---------------------------------------------------------------------------
// Kernel 3: V_predict_new = V_predict + V_w * L_vert
// ---------------------------------------------------------------------------
__global__ void k_epi(const float* __restrict__ Vp,
                      const float* __restrict__ Vw,
                      float*       __restrict__ out)     // (B,NV,3) at d_out
{
    int tid = blockIdx.x * blockDim.x + threadIdx.x;
    if (tid >= BB * NVV) return;
    int b = tid / NVV;
    int n = tid - b * NVV;
    float w = Vw[tid];
    size_t o = (size_t)tid * 3;
    out[o + 0] = Vp[o + 0] + w * g_Lv[(size_t)(b * 3 + 0) * NVV + n];
    out[o + 1] = Vp[o + 1] + w * g_Lv[(size_t)(b * 3 + 1) * NVV + n];
    out[o + 2] = Vp[o + 2] + w * g_Lv[(size_t)(b * 3 + 2) * NVV + n];
}

// ---------------------------------------------------------------------------
extern "C" void kernel_launch(void* const* d_in, const int* in_sizes, int n_in,
                              void* d_out, int out_size)
{
    const float* Vp  = (const float*)d_in[0];   // V_predict    (B,NV,3)
    const float* L   = (const float*)d_in[1];   // L            (B,E,1)
    const float* Vw  = (const float*)d_in[2];   // V_w          (B,NV,1)
    const float* Vc  = (const float*)d_in[3];   // V_compliance (B,1,1)
    const int*   Cd  = (const int*)  d_in[4];   // C_dist       (E,2)
    const float* Cid = (const float*)d_in[5];   // C_init_d     (E,1)
    const float* Cm  = (const float*)d_in[6];   // C_mtx        (E,NV)

    float* out_vp = (float*)d_out;                         // V_predict_new
    float* out_L  = (float*)d_out + (size_t)BB * NVV * 3;  // L_new

    // 0) zero accumulator
    k_zero<<<(24 * NVV + 255) / 256, 256>>>();

    // 1) edge solve -> M, L_new
    k_edge<<<(BB * EE + 255) / 256, 256>>>(Vp, L, Vw, Vc, Cd, Cid, out_L);

    // 2) tall-skinny GEMM: Lv = M^T @ C_mtx
    dim3 g(NVV / (GEMM_THREADS * 4), EE / E_CHUNK);  // (16, 32)
    k_gemm<<<g, GEMM_THREADS>>>(Cm);

    // 3) vertex update
    k_epi<<<(BB * NVV + 255) / 256, 256>>>(Vp, Vw, out_vp);
}

// round 6
// speedup vs baseline: 1.6934x; 1.6644x over previous
#include <cuda_runtime.h>
#include <cstdint>

// Problem constants (fixed shapes from reference)
#define BB 8
#define NVV 8192
#define EE 32768

typedef unsigned long long ull;

// Scratch (no cudaMalloc allowed): M in (e, bc) layout + L_vert accumulator
__device__ float g_M[EE * 24];       // 3 MB:  M[e][b*3+c]
__device__ float g_Lv[24 * NVV];     // 768 KB: Lv[bc][n]

// ---------------------------------------------------------------------------
// Kernel 0: zero the L_vert accumulator (graph replays re-run this each launch)
// ---------------------------------------------------------------------------
__global__ void k_zero() {
    int t = blockIdx.x * blockDim.x + threadIdx.x;
    if (t < 24 * NVV) g_Lv[t] = 0.0f;
}

// ---------------------------------------------------------------------------
// Kernel 1: per-(b,e) constraint solve -> L_new (into d_out tail) + M scratch
// ---------------------------------------------------------------------------
__global__ void k_edge(const float* __restrict__ Vp,     // (B,NV,3)
                       const float* __restrict__ L,      // (B,E,1)
                       const float* __restrict__ Vw,     // (B,NV,1)
                       const float* __restrict__ Vc,     // (B,1,1)
                       const int*   __restrict__ Cd,     // (E,2)
                       const float* __restrict__ Cid,    // (E,1)
                       float*       __restrict__ Lnew)   // (B,E) at d_out + B*NV*3
{
    int tid = blockIdx.x * blockDim.x + threadIdx.x;
    if (tid >= BB * EE) return;
    int b = tid / EE;
    int e = tid - b * EE;

    int i = Cd[2 * e];
    int j = Cd[2 * e + 1];

    const float* pi = Vp + ((size_t)b * NVV + i) * 3;
    const float* pj = Vp + ((size_t)b * NVV + j) * 3;
    float nx = pi[0] - pj[0];
    float ny = pi[1] - pj[1];
    float nz = pi[2] - pj[2];
    float D = sqrtf(nx * nx + ny * ny + nz * nz);
    float C = D - Cid[e];

    float A = Vc[b];
    float S = Vw[b * NVV + i] + Vw[b * NVV + j];
    float Seff = (S == 0.0f) ? __int_as_float(0x7f800000) : S;   // inf where S==0
    float denom = Seff + A;

    float l  = L[tid];                  // L is (B,E) contiguous, tid = b*E+e
    float ld = (-C - A * l) / denom;    // -> 0 when denom == inf
    Lnew[tid] = l + ld;

    float inv = ld / (D + 1e-8f);       // L_delta * N_norm
    int mb = e * 24 + b * 3;
    g_M[mb + 0] = inv * nx;
    g_M[mb + 1] = inv * ny;
    g_M[mb + 2] = inv * nz;
}

// ---------------------------------------------------------------------------
// Kernel 2: Lv[bc][n] = sum_e M[e][bc] * C_mtx[e][n]
// Tall-skinny GEMM (24 x E) * (E x NV) with packed fp32x2 FMA.
//
// v2 design (fixing the R3 wave-quantization + register-pressure losses):
//  - 128 threads/block, 2 columns/thread (24 ULL accumulators = 48 regs)
//  - persistent grid of exactly 592 blocks (148 SMs x 4, pinned via
//    __launch_bounds__(128,4)) -> single balanced wave, no 2x wave cliff
//  - 4096 fine-grained work items (32 n-blocks x 128 e-chunks of 256),
//    strided item loop -> <=1% load imbalance
//  - M staged in SMEM as duplicated (m,m) 64-bit pairs, read 2-at-a-time via
//    LDS.128 (12 LDS per e instead of 24)
//  - __ldcs streaming loads for the 1 GiB C_mtx (read-once, don't thrash L2)
//  - float atomic RED combine into g_Lv across e-chunks
// ---------------------------------------------------------------------------
#define GT 128                       // threads per block
#define TILE_N (GT * 2)              // 256 columns per block
#define E_TILE 64                    // e rows staged per barrier
#define E_CHUNK 256                  // e rows per work item
#define N_BLKS (NVV / TILE_N)        // 32
#define E_BLKS (EE / E_CHUNK)        // 128
#define N_ITEMS (N_BLKS * E_BLKS)    // 4096
#define GRID_G 592                   // 148 SMs * 4 blocks

__global__ void __launch_bounds__(GT, 4)
k_gemm(const float* __restrict__ Cm)   // C_mtx (E, NV) row-major
{
    __shared__ ull Ms[E_TILE][24];     // (m,m) duplicated pairs, rows 16B-aligned

    const int t = threadIdx.x;

    for (int item = blockIdx.x; item < N_ITEMS; item += GRID_G) {
        const int nb = item & (N_BLKS - 1);
        const int eb = item >> 5;                 // item / N_BLKS
        const int n0 = nb * TILE_N + t * 2;
        const int e0 = eb * E_CHUNK;

        ull acc[24];
#pragma unroll
        for (int bc = 0; bc < 24; bc++) acc[bc] = 0ull;

        for (int et = 0; et < E_CHUNK; et += E_TILE) {
            // Stage E_TILE*24 = 1536 M values as duplicated f32x2 pairs
            const float* msrc = g_M + (size_t)(e0 + et) * 24;
#pragma unroll
            for (int k = t; k < E_TILE * 24; k += GT) {
                ull d = (ull)__float_as_uint(msrc[k]);
                d |= d << 32;
                ((ull*)Ms)[k] = d;
            }
            __syncthreads();

            const float* p = Cm + (size_t)(e0 + et) * NVV + n0;
#pragma unroll 4
            for (int ee = 0; ee < E_TILE; ee++) {
                // 8B coalesced streaming load: 2 consecutive columns of row e
                ull cv = __ldcs(reinterpret_cast<const ull*>(p));
                p += NVV;
#pragma unroll
                for (int bc = 0; bc < 24; bc += 2) {
                    ulonglong2 mm =
                        *reinterpret_cast<const ulonglong2*>(&Ms[ee][bc]);
                    asm("fma.rn.f32x2 %0, %1, %2, %0;"
                        : "+l"(acc[bc])     : "l"(mm.x), "l"(cv));
                    asm("fma.rn.f32x2 %0, %1, %2, %0;"
                        : "+l"(acc[bc + 1]) : "l"(mm.y), "l"(cv));
                }
            }
            __syncthreads();
        }

        // Combine partials across e-chunks (spread-address float REDs)
#pragma unroll
        for (int bc = 0; bc < 24; bc++) {
            float* dst = g_Lv + (size_t)bc * NVV + n0;
            atomicAdd(dst + 0, __uint_as_float((unsigned)(acc[bc] & 0xffffffffu)));
            atomicAdd(dst + 1, __uint_as_float((unsigned)(acc[bc] >> 32)));
        }
    }
}

// ---------------------------------------------------------------------------
// Kernel 3: V_predict_new = V_predict + V_w * L_vert
// ---------------------------------------------------------------------------
__global__ void k_epi(const float* __restrict__ Vp,
                      const float* __restrict__ Vw,
                      float*       __restrict__ out)     // (B,NV,3) at d_out
{
    int tid = blockIdx.x * blockDim.x + threadIdx.x;
    if (tid >= BB * NVV) return;
    int b = tid / NVV;
    int n = tid - b * NVV;
    float w = Vw[tid];
    size_t o = (size_t)tid * 3;
    out[o + 0] = Vp[o + 0] + w * g_Lv[(size_t)(b * 3 + 0) * NVV + n];
    out[o + 1] = Vp[o + 1] + w * g_Lv[(size_t)(b * 3 + 1) * NVV + n];
    out[o + 2] = Vp[o + 2] + w * g_Lv[(size_t)(b * 3 + 2) * NVV + n];
}

// ---------------------------------------------------------------------------
extern "C" void kernel_launch(void* const* d_in, const int* in_sizes, int n_in,
                              void* d_out, int out_size)
{
    const float* Vp  = (const float*)d_in[0];   // V_predict    (B,NV,3)
    const float* L   = (const float*)d_in[1];   // L            (B,E,1)
    const float* Vw  = (const float*)d_in[2];   // V_w          (B,NV,1)
    const float* Vc  = (const float*)d_in[3];   // V_compliance (B,1,1)
    const int*   Cd  = (const int*)  d_in[4];   // C_dist       (E,2)
    const float* Cid = (const float*)d_in[5];   // C_init_d     (E,1)
    const float* Cm  = (const float*)d_in[6];   // C_mtx        (E,NV)

    float* out_vp = (float*)d_out;                         // V_predict_new
    float* out_L  = (float*)d_out + (size_t)BB * NVV * 3;  // L_new

    // 0) zero accumulator
    k_zero<<<(24 * NVV + 255) / 256, 256>>>();

    // 1) edge solve -> M, L_new
    k_edge<<<(BB * EE + 255) / 256, 256>>>(Vp, L, Vw, Vc, Cd, Cid, out_L);

    // 2) tall-skinny GEMM: Lv = M^T @ C_mtx  (persistent, single wave)
    k_gemm<<<GRID_G, GT>>>(Cm);

    // 3) vertex update
    k_epi<<<(BB * NVV + 255) / 256, 256>>>(Vp, Vw, out_vp);
}

// round 7
// speedup vs baseline: 1.6952x; 1.0010x over previous
#include <cuda_runtime.h>
#include <cstdint>

// Problem constants (fixed shapes from reference)
#define BB 8
#define NVV 8192
#define EE 32768

typedef unsigned long long ull;

// Scratch (no cudaMalloc allowed): M in (e, bc) layout + L_vert accumulator
__device__ float g_M[EE * 24];       // 3 MB:  M[e][b*3+c]
__device__ float g_Lv[24 * NVV];     // 768 KB: Lv[bc][n]

// ---------------------------------------------------------------------------
// Kernel 0: zero the L_vert accumulator (graph replays re-run this each launch)
// ---------------------------------------------------------------------------
__global__ void k_zero() {
    int t = blockIdx.x * blockDim.x + threadIdx.x;
    if (t < 24 * NVV) g_Lv[t] = 0.0f;
}

// ---------------------------------------------------------------------------
// Kernel 1: per-(b,e) constraint solve -> L_new (into d_out tail) + M scratch
// ---------------------------------------------------------------------------
__global__ void k_edge(const float* __restrict__ Vp,     // (B,NV,3)
                       const float* __restrict__ L,      // (B,E,1)
                       const float* __restrict__ Vw,     // (B,NV,1)
                       const float* __restrict__ Vc,     // (B,1,1)
                       const int*   __restrict__ Cd,     // (E,2)
                       const float* __restrict__ Cid,    // (E,1)
                       float*       __restrict__ Lnew)   // (B,E) at d_out + B*NV*3
{
    int tid = blockIdx.x * blockDim.x + threadIdx.x;
    if (tid >= BB * EE) return;
    int b = tid / EE;
    int e = tid - b * EE;

    int i = Cd[2 * e];
    int j = Cd[2 * e + 1];

    const float* pi = Vp + ((size_t)b * NVV + i) * 3;
    const float* pj = Vp + ((size_t)b * NVV + j) * 3;
    float nx = pi[0] - pj[0];
    float ny = pi[1] - pj[1];
    float nz = pi[2] - pj[2];
    float D = sqrtf(nx * nx + ny * ny + nz * nz);
    float C = D - Cid[e];

    float A = Vc[b];
    float S = Vw[b * NVV + i] + Vw[b * NVV + j];
    float Seff = (S == 0.0f) ? __int_as_float(0x7f800000) : S;   // inf where S==0
    float denom = Seff + A;

    float l  = L[tid];                  // L is (B,E) contiguous, tid = b*E+e
    float ld = (-C - A * l) / denom;    // -> 0 when denom == inf
    Lnew[tid] = l + ld;

    float inv = ld / (D + 1e-8f);       // L_delta * N_norm
    int mb = e * 24 + b * 3;
    g_M[mb + 0] = inv * nx;
    g_M[mb + 1] = inv * ny;
    g_M[mb + 2] = inv * nz;
}

// ---------------------------------------------------------------------------
// Kernel 2: Lv[bc][n] = sum_e M[e][bc] * C_mtx[e][n]
// Tall-skinny GEMM (24 x E) * (E x NV) with packed fp32x2 FMA.
//
// v2 design (fixing the R3 wave-quantization + register-pressure losses):
//  - 128 threads/block, 2 columns/thread (24 ULL accumulators = 48 regs)
//  - persistent grid of exactly 592 blocks (148 SMs x 4, pinned via
//    __launch_bounds__(128,4)) -> single balanced wave, no 2x wave cliff
//  - 4096 fine-grained work items (32 n-blocks x 128 e-chunks of 256),
//    strided item loop -> <=1% load imbalance
//  - M staged in SMEM as duplicated (m,m) 64-bit pairs, read 2-at-a-time via
//    LDS.128 (12 LDS per e instead of 24)
//  - __ldcs streaming loads for the 1 GiB C_mtx (read-once, don't thrash L2)
//  - float atomic RED combine into g_Lv across e-chunks
// ---------------------------------------------------------------------------
#define GT 128                       // threads per block
#define TILE_N (GT * 2)              // 256 columns per block
#define E_TILE 64                    // e rows staged per barrier
#define E_CHUNK 256                  // e rows per work item
#define N_BLKS (NVV / TILE_N)        // 32
#define E_BLKS (EE / E_CHUNK)        // 128
#define N_ITEMS (N_BLKS * E_BLKS)    // 4096
#define GRID_G 592                   // 148 SMs * 4 blocks

__global__ void __launch_bounds__(GT, 4)
k_gemm(const float* __restrict__ Cm)   // C_mtx (E, NV) row-major
{
    __shared__ ull Ms[E_TILE][24];     // (m,m) duplicated pairs, rows 16B-aligned

    const int t = threadIdx.x;

    for (int item = blockIdx.x; item < N_ITEMS; item += GRID_G) {
        const int nb = item & (N_BLKS - 1);
        const int eb = item >> 5;                 // item / N_BLKS
        const int n0 = nb * TILE_N + t * 2;
        const int e0 = eb * E_CHUNK;

        ull acc[24];
#pragma unroll
        for (int bc = 0; bc < 24; bc++) acc[bc] = 0ull;

        for (int et = 0; et < E_CHUNK; et += E_TILE) {
            // Stage E_TILE*24 = 1536 M values as duplicated f32x2 pairs
            const float* msrc = g_M + (size_t)(e0 + et) * 24;
#pragma unroll
            for (int k = t; k < E_TILE * 24; k += GT) {
                ull d = (ull)__float_as_uint(msrc[k]);
                d |= d << 32;
                ((ull*)Ms)[k] = d;
            }
            __syncthreads();

            const float* p = Cm + (size_t)(e0 + et) * NVV + n0;
#pragma unroll 4
            for (int ee = 0; ee < E_TILE; ee++) {
                // 8B coalesced streaming load: 2 consecutive columns of row e
                ull cv = __ldcs(reinterpret_cast<const ull*>(p));
                p += NVV;
#pragma unroll
                for (int bc = 0; bc < 24; bc += 2) {
                    ulonglong2 mm =
                        *reinterpret_cast<const ulonglong2*>(&Ms[ee][bc]);
                    asm("fma.rn.f32x2 %0, %1, %2, %0;"
                        : "+l"(acc[bc])     : "l"(mm.x), "l"(cv));
                    asm("fma.rn.f32x2 %0, %1, %2, %0;"
                        : "+l"(acc[bc + 1]) : "l"(mm.y), "l"(cv));
                }
            }
            __syncthreads();
        }

        // Combine partials across e-chunks (spread-address float REDs)
#pragma unroll
        for (int bc = 0; bc < 24; bc++) {
            float* dst = g_Lv + (size_t)bc * NVV + n0;
            atomicAdd(dst + 0, __uint_as_float((unsigned)(acc[bc] & 0xffffffffu)));
            atomicAdd(dst + 1, __uint_as_float((unsigned)(acc[bc] >> 32)));
        }
    }
}

// ---------------------------------------------------------------------------
// Kernel 3: V_predict_new = V_predict + V_w * L_vert
// ---------------------------------------------------------------------------
__global__ void k_epi(const float* __restrict__ Vp,
                      const float* __restrict__ Vw,
                      float*       __restrict__ out)     // (B,NV,3) at d_out
{
    int tid = blockIdx.x * blockDim.x + threadIdx.x;
    if (tid >= BB * NVV) return;
    int b = tid / NVV;
    int n = tid - b * NVV;
    float w = Vw[tid];
    size_t o = (size_t)tid * 3;
    out[o + 0] = Vp[o + 0] + w * g_Lv[(size_t)(b * 3 + 0) * NVV + n];
    out[o + 1] = Vp[o + 1] + w * g_Lv[(size_t)(b * 3 + 1) * NVV + n];
    out[o + 2] = Vp[o + 2] + w * g_Lv[(size_t)(b * 3 + 2) * NVV + n];
}

// ---------------------------------------------------------------------------
extern "C" void kernel_launch(void* const* d_in, const int* in_sizes, int n_in,
                              void* d_out, int out_size)
{
    const float* Vp  = (const float*)d_in[0];   // V_predict    (B,NV,3)
    const float* L   = (const float*)d_in[1];   // L            (B,E,1)
    const float* Vw  = (const float*)d_in[2];   // V_w          (B,NV,1)
    const float* Vc  = (const float*)d_in[3];   // V_compliance (B,1,1)
    const int*   Cd  = (const int*)  d_in[4];   // C_dist       (E,2)
    const float* Cid = (const float*)d_in[5];   // C_init_d     (E,1)
    const float* Cm  = (const float*)d_in[6];   // C_mtx        (E,NV)

    float* out_vp = (float*)d_out;                         // V_predict_new
    float* out_L  = (float*)d_out + (size_t)BB * NVV * 3;  // L_new

    // 0) zero accumulator
    k_zero<<<(24 * NVV + 255) / 256, 256>>>();

    // 1) edge solve -> M, L_new
    k_edge<<<(BB * EE + 255) / 256, 256>>>(Vp, L, Vw, Vc, Cd, Cid, out_L);

    // 2) tall-skinny GEMM: Lv = M^T @ C_mtx  (persistent, single wave)
    k_gemm<<<GRID_G, GT>>>(Cm);

    // 3) vertex update
    k_epi<<<(BB * NVV + 255) / 256, 256>>>(Vp, Vw, out_vp);
}